// round 16
// baseline (speedup 1.0000x reference)
#include <cuda_runtime.h>
#include <cuda_fp16.h>
#include <cstdint>

// ---------------------------------------------------------------- problem dims
constexpr int Bb   = 2;
constexpr int Tt   = 2048;
constexpr int Dd   = 1024;
constexpr int Hh   = 16;
constexpr int HDim = 64;
constexpr int BT   = Bb * Tt;      // 4096
constexpr int BHn  = Bb * Hh;      // 32
constexpr int CH   = 64;           // chunk length (attention)
constexpr int NCH  = Tt / CH;      // 32

// ---------------------------------------------------------------- scratch
__device__ float  g_Q[BHn * Tt * HDim];
__device__ float  g_K[BHn * Tt * HDim];
__device__ float  g_V[BHn * Tt * HDim];
__device__ float  g_cs[BHn * NCH * HDim * HDim];
__device__ float  g_sp[BHn * NCH * HDim * HDim];
__device__ __half g_X16[BT * Dd];          // fp16 input activations
__device__ __half g_W16[4 * Dd * Dd];      // fp16 weights (q,k,v,o)
__device__ __half g_Y16[BT * Dd];          // fp16 attention output, row-major

extern __shared__ char dyn_smem[];

// ---------------------------------------------------------------- helpers
// pack two floats to fp16x2: low half = lo_val, high half = hi_val
__device__ __forceinline__ uint32_t packh(float lo_val, float hi_val) {
    uint32_t r;
    asm("cvt.rn.f16x2.f32 %0, %1, %2;" : "=r"(r) : "f"(hi_val), "f"(lo_val));
    return r;
}
__device__ __forceinline__ float2 unpackh(uint32_t h) {
    __half2 hh = *reinterpret_cast<__half2*>(&h);
    return __half22float2(hh);
}

__device__ __forceinline__ void mma_f16(float* c, const uint32_t* a, const uint32_t* b) {
    asm volatile(
        "mma.sync.aligned.m16n8k16.row.col.f32.f16.f16.f32 "
        "{%0,%1,%2,%3}, {%4,%5,%6,%7}, {%8,%9}, {%0,%1,%2,%3};"
        : "+f"(c[0]), "+f"(c[1]), "+f"(c[2]), "+f"(c[3])
        : "r"(a[0]), "r"(a[1]), "r"(a[2]), "r"(a[3]), "r"(b[0]), "r"(b[1]));
}

__device__ __forceinline__ void ldmx4(uint32_t* r, uint32_t saddr) {
    asm volatile("ldmatrix.sync.aligned.m8n8.x4.shared.b16 {%0,%1,%2,%3}, [%4];"
                 : "=r"(r[0]), "=r"(r[1]), "=r"(r[2]), "=r"(r[3]) : "r"(saddr));
}
__device__ __forceinline__ void ldmx4t(uint32_t* r, uint32_t saddr) {
    asm volatile("ldmatrix.sync.aligned.m8n8.x4.trans.shared.b16 {%0,%1,%2,%3}, [%4];"
                 : "=r"(r[0]), "=r"(r[1]), "=r"(r[2]), "=r"(r[3]) : "r"(saddr));
}

// ---------------------------------------------------------------- converters
__global__ __launch_bounds__(256) void convert_x(const float4* __restrict__ src)
{
    int i = blockIdx.x * 256 + threadIdx.x;          // over BT*Dd/4
    float4 v = src[i];
    ((uint2*)g_X16)[i] = make_uint2(packh(v.x, v.y), packh(v.z, v.w));
}
__global__ __launch_bounds__(256) void convert_w(const float4* __restrict__ w0,
                                                 const float4* __restrict__ w1,
                                                 const float4* __restrict__ w2,
                                                 const float4* __restrict__ w3)
{
    int z = blockIdx.y;
    const float4* src = (z == 0) ? w0 : (z == 1) ? w1 : (z == 2) ? w2 : w3;
    int i = blockIdx.x * 256 + threadIdx.x;          // over Dd*Dd/4
    float4 v = src[i];
    ((uint2*)g_W16)[(size_t)z * (Dd * Dd / 4) + i] = make_uint2(packh(v.x, v.y), packh(v.z, v.w));
}

// ---------------------------------------------------------------- tc_gemm cfg
constexpr int TM = 128, TN = 128, KC = 32;   // CTA tile + K chunk
constexpr int NKC = Dd / KC;                 // 32
constexpr int PAD_K = 40;                    // fp16 row stride (conflict-free)
constexpr int TILE_B = 128 * PAD_K * 2;      // 10240 bytes per fp16 tile
constexpr int OFF_A = 0;
constexpr int OFF_B = TILE_B;
constexpr int BUF_B = 2 * TILE_B;            // 20480 per stage
constexpr int STAGES = 3;
constexpr int GEMM_SMEM = STAGES * BUF_B;    // 61440 (dynamic, 3-stage cp.async)

// ---------------------------------------------------------------------------
// Tensor-core GEMM, fp16 operands, cp.async 3-stage pipeline:
//   out[m,n] = sum_k A16[m,k] * W16[widx][n,k] + bias[n]
// mode 0: A = g_X16, widx = z, dst = g_Q/g_K/g_V head-major fp32
// mode 1: A = g_Y16, widx = 3, dst = outp row-major fp32
// ---------------------------------------------------------------------------
__global__ __launch_bounds__(256) void tc_gemm(const float* __restrict__ b0p,
                                               const float* __restrict__ b1p,
                                               const float* __restrict__ b2p,
                                               float* __restrict__ outp,
                                               int mode)
{
    char* smem = dyn_smem;
    const int tid  = threadIdx.x;
    const int wid  = tid >> 5;
    const int lane = tid & 31;
    const int z    = blockIdx.z;
    const int bn = blockIdx.x * TN;
    const int bm = blockIdx.y * TM;
    const int widx = (mode == 0) ? z : 3;
    const float* bias = (z == 0) ? b0p : (z == 1) ? b1p : b2p;
    const __half* A16 = (mode == 0) ? g_X16 : g_Y16;
    const __half* W16 = g_W16 + (size_t)widx * Dd * Dd;

    uint32_t sbase;
    asm("{ .reg .u64 t; cvta.to.shared.u64 t, %1; cvt.u32.u64 %0, t; }"
        : "=r"(sbase) : "l"((const void*)smem));

    const int m0w = (wid >> 2) * 64;      // warp row offset
    const int n0w = (wid & 3) * 32;       // warp col offset
    const int lrow  = lane >> 2;
    const int lcol2 = (lane & 3) * 2;

    const uint32_t a_lane = (uint32_t)(((m0w + ((lane >> 3) & 1) * 8 + (lane & 7)) * PAD_K
                                        + (lane >> 4) * 8) * 2);
    const uint32_t b_lane = (uint32_t)(((n0w + (lane >> 4) * 8 + (lane & 7)) * PAD_K
                                        + ((lane >> 3) & 1) * 8) * 2);

    float c[4][4][4];
#pragma unroll
    for (int mi = 0; mi < 4; mi++)
#pragma unroll
        for (int ni = 0; ni < 4; ni++)
#pragma unroll
            for (int r = 0; r < 4; r++) c[mi][ni][r] = 0.0f;

    const int row_ld = tid >> 2;
    const int cg     = (tid & 3) * 8;

    auto issue_copy = [&](int ck) {
        const int k0 = ck * KC;
        const uint32_t bo = (uint32_t)((ck % STAGES) * BUF_B);
#pragma unroll
        for (int t = 0; t < 2; t++) {
            int row = row_ld + t * 64;
            uint32_t soff = (uint32_t)((row * PAD_K + cg) * 2);
            const __half* ga = A16 + (size_t)(bm + row) * Dd + k0 + cg;
            const __half* gb = W16 + (size_t)(bn + row) * Dd + k0 + cg;
            uint32_t sa = sbase + bo + OFF_A + soff;
            uint32_t sb = sbase + bo + OFF_B + soff;
            asm volatile("cp.async.cg.shared.global [%0], [%1], 16;" :: "r"(sa), "l"(ga));
            asm volatile("cp.async.cg.shared.global [%0], [%1], 16;" :: "r"(sb), "l"(gb));
        }
        asm volatile("cp.async.commit_group;" ::: "memory");
    };

    issue_copy(0);
    issue_copy(1);

    for (int ck = 0; ck < NKC; ck++) {
        if (ck + 2 < NKC) {
            asm volatile("cp.async.wait_group 1;" ::: "memory");
        } else {
            asm volatile("cp.async.wait_group 0;" ::: "memory");
        }
        __syncthreads();
        if (ck + 2 < NKC) issue_copy(ck + 2);

        const uint32_t bo = (uint32_t)((ck % STAGES) * BUF_B);
#pragma unroll
        for (int kk = 0; kk < KC; kk += 16) {
            uint32_t ah[4][4];
#pragma unroll
            for (int mi = 0; mi < 4; mi++)
                ldmx4(ah[mi], sbase + bo + OFF_A + a_lane + (uint32_t)((mi * 16 * PAD_K + kk) * 2));
            uint32_t bh[4][2];
#pragma unroll
            for (int np = 0; np < 2; np++) {
                uint32_t r[4];
                ldmx4(r, sbase + bo + OFF_B + b_lane + (uint32_t)((np * 16 * PAD_K + kk) * 2));
                bh[np * 2][0] = r[0]; bh[np * 2][1] = r[1];
                bh[np * 2 + 1][0] = r[2]; bh[np * 2 + 1][1] = r[3];
            }
#pragma unroll
            for (int mi = 0; mi < 4; mi++)
#pragma unroll
                for (int ni = 0; ni < 4; ni++)
                    mma_f16(c[mi][ni], ah[mi], bh[ni]);
        }
    }

    // ---- epilogue
#pragma unroll
    for (int mi = 0; mi < 4; mi++) {
        int row0 = bm + m0w + mi * 16 + lrow;
        int row1 = row0 + 8;
#pragma unroll
        for (int ni = 0; ni < 4; ni++) {
            int n = bn + n0w + ni * 8 + lcol2;
            float bb0 = bias[n], bb1 = bias[n + 1];
            float2 v0 = make_float2(c[mi][ni][0] + bb0, c[mi][ni][1] + bb1);
            float2 v1 = make_float2(c[mi][ni][2] + bb0, c[mi][ni][3] + bb1);
            if (mode == 0) {
                float* base = (z == 0) ? g_Q : (z == 1) ? g_K : g_V;
                int h = n >> 6, hd = n & 63;
                int batch0 = row0 >> 11, t0 = row0 & 2047;
                int batch1 = row1 >> 11, t1 = row1 & 2047;
                *(float2*)(base + (((size_t)(batch0 * Hh + h) * Tt) + t0) * HDim + hd) = v0;
                *(float2*)(base + (((size_t)(batch1 * Hh + h) * Tt) + t1) * HDim + hd) = v1;
            } else {
                *(float2*)(outp + (size_t)row0 * Dd + n) = v0;
                *(float2*)(outp + (size_t)row1 * Dd + n) = v1;
            }
        }
    }
}

// ---------------------------------------------------------------- tile cfg
constexpr int TPAD = 72;                     // 144B stride -> conflict-free ldmatrix
constexpr int T_TILE2 = 64 * TPAD * 2;       // 9216 B

// ---------------------------------------------------------------------------
// Tensor-core chunk sums: cs[p][n] = sum_t V[t][p] * K[t][n]
// K/V stored ROW-MAJOR hi/lo (vectorized stores); BOTH fragments loaded with
// ldmatrix.trans (no transposed stores). 3-term split -> fp32-grade.
// Warp grid 4x2: mw = (wid>>1)*16 p-rows, nw = (wid&1)*32 n-cols.
// ---------------------------------------------------------------------------
constexpr int OFF_CVH = 0;
constexpr int OFF_CVL = 1 * T_TILE2;
constexpr int OFF_CKH = 2 * T_TILE2;
constexpr int OFF_CKL = 3 * T_TILE2;
constexpr int CS_SMEM = 4 * T_TILE2;         // 36864 B

__global__ __launch_bounds__(256) void chunk_sums_tc()
{
    char* smem = dyn_smem;
    uint32_t sbase;
    asm("{ .reg .u64 t; cvta.to.shared.u64 t, %1; cvt.u32.u64 %0, t; }"
        : "=r"(sbase) : "l"((const void*)smem));
    const int bh = blockIdx.y, c = blockIdx.x;
    const int tid = threadIdx.x;
    const int wid = tid >> 5;
    const int lane = tid & 31;
    const float* Kg = g_K + ((size_t)bh * Tt + c * CH) * HDim;
    const float* Vg = g_V + ((size_t)bh * Tt + c * CH) * HDim;

    __half* sVh = (__half*)(smem + OFF_CVH);
    __half* sVl = (__half*)(smem + OFF_CVL);
    __half* sKh = (__half*)(smem + OFF_CKH);
    __half* sKl = (__half*)(smem + OFF_CKL);

    // row-major hi/lo stores (conflict-free vectorized pattern)
    for (int i = tid; i < 1024; i += 256) {
        int r = i >> 4;               // t 0..63
        int c4 = (i & 15) << 2;       // col base (p / n)
        float4 v = *(const float4*)(Vg + r * 64 + c4);
        float4 k = *(const float4*)(Kg + r * 64 + c4);
        {
            uint32_t h01 = packh(v.x, v.y), h23 = packh(v.z, v.w);
            float2 f01 = unpackh(h01), f23 = unpackh(h23);
            *(uint2*)(sVh + r * TPAD + c4) = make_uint2(h01, h23);
            *(uint2*)(sVl + r * TPAD + c4) =
                make_uint2(packh(v.x - f01.x, v.y - f01.y), packh(v.z - f23.x, v.w - f23.y));
        }
        {
            uint32_t h01 = packh(k.x, k.y), h23 = packh(k.z, k.w);
            float2 f01 = unpackh(h01), f23 = unpackh(h23);
            *(uint2*)(sKh + r * TPAD + c4) = make_uint2(h01, h23);
            *(uint2*)(sKl + r * TPAD + c4) =
                make_uint2(packh(k.x - f01.x, k.y - f01.y), packh(k.z - f23.x, k.w - f23.y));
        }
    }
    __syncthreads();

    const int mw = (wid >> 1) * 16;       // p base
    const int nw = (wid & 1) * 32;        // n base
    const int lrow  = lane >> 2;
    const int lcol2 = (lane & 3) * 2;

    // trans A (V^T): rows t = (lane>>4)*8 + (lane&7); col p = mw + ((lane>>3)&1)*8
    const uint32_t at_lane = (uint32_t)((((lane >> 4) * 8 + (lane & 7)) * TPAD
                                         + mw + ((lane >> 3) & 1) * 8) * 2);
    // trans B (K^T): rows t = ((lane>>3)&1)*8 + (lane&7); col n = nw + (lane>>4)*8
    const uint32_t bt_lane = (uint32_t)(((((lane >> 3) & 1) * 8 + (lane & 7)) * TPAD
                                         + nw + (lane >> 4) * 8) * 2);

    float acc[4][4];
#pragma unroll
    for (int ni = 0; ni < 4; ni++)
#pragma unroll
        for (int r = 0; r < 4; r++) acc[ni][r] = 0.0f;
#pragma unroll
    for (int kk = 0; kk < 64; kk += 16) {
        uint32_t vh[4], vl[4];
        uint32_t ad = sbase + OFF_CVH + at_lane + (uint32_t)(kk * TPAD * 2);
        ldmx4t(vh, ad);
        ldmx4t(vl, ad + (OFF_CVL - OFF_CVH));
        uint32_t kh[4][2], kl[4][2];
#pragma unroll
        for (int np = 0; np < 2; np++) {
            uint32_t bd = sbase + OFF_CKH + bt_lane + (uint32_t)((kk * TPAD + np * 16) * 2);
            uint32_t r4[4];
            ldmx4t(r4, bd);
            kh[np * 2][0] = r4[0]; kh[np * 2][1] = r4[1];
            kh[np * 2 + 1][0] = r4[2]; kh[np * 2 + 1][1] = r4[3];
            ldmx4t(r4, bd + (OFF_CKL - OFF_CKH));
            kl[np * 2][0] = r4[0]; kl[np * 2][1] = r4[1];
            kl[np * 2 + 1][0] = r4[2]; kl[np * 2 + 1][1] = r4[3];
        }
#pragma unroll
        for (int ni = 0; ni < 4; ni++) {
            mma_f16(acc[ni], vh, kh[ni]);
            mma_f16(acc[ni], vh, kl[ni]);
            mma_f16(acc[ni], vl, kh[ni]);
        }
    }

    float* dst = g_cs + ((size_t)bh * NCH + c) * 4096;
#pragma unroll
    for (int ni = 0; ni < 4; ni++) {
        int n = nw + ni * 8 + lcol2;
        int p0 = mw + lrow, p1 = p0 + 8;
        *(float2*)(dst + p0 * 64 + n) = make_float2(acc[ni][0], acc[ni][1]);
        *(float2*)(dst + p1 * 64 + n) = make_float2(acc[ni][2], acc[ni][3]);
    }
}

// ---------------------------------------------------------------------------
// Exclusive prefix over chunks (parallelized: 512 blocks)
// ---------------------------------------------------------------------------
__global__ __launch_bounds__(256) void prefix_kernel()
{
    const int bh = blockIdx.x;
    const int e = blockIdx.y * 256 + threadIdx.x;
    float acc = 0.0f;
#pragma unroll
    for (int c = 0; c < NCH; c++) {
        size_t off = ((size_t)bh * NCH + c) * 4096 + e;
        g_sp[off] = acc;
        acc += g_cs[off];
    }
}

// ---------------------------------------------------------------------------
// Tensor-core intra-chunk attention, FULL 2-term split on ALL operands.
// V stored ROW-MAJOR hi/lo; its B-fragment loaded with ldmatrix.trans.
//   scores A[t][s] = mask(Q[t]·K[s]);  Y[t][p] = A·V + Q·Sp^T
// Output written fp16 row-major to g_Y16.
// ---------------------------------------------------------------------------
constexpr int OFF_QH2  = 0;
constexpr int OFF_QL2  = 1 * T_TILE2;
constexpr int OFF_KH2  = 2 * T_TILE2;
constexpr int OFF_KL2  = 3 * T_TILE2;
constexpr int OFF_VH2  = 4 * T_TILE2;
constexpr int OFF_VL2  = 5 * T_TILE2;
constexpr int OFF_SPH2 = 6 * T_TILE2;
constexpr int OFF_SPL2 = 7 * T_TILE2;
constexpr int OFF_AH2  = OFF_KH2;            // aliases
constexpr int OFF_AL2  = OFF_KL2;
constexpr int ATTN_SMEM = 8 * T_TILE2;       // 73728 B

__global__ __launch_bounds__(256) void attn_tc()
{
    char* smem = dyn_smem;
    uint32_t sbase;
    asm("{ .reg .u64 t; cvta.to.shared.u64 t, %1; cvt.u32.u64 %0, t; }"
        : "=r"(sbase) : "l"((const void*)smem));
    const int bh = blockIdx.y, c = blockIdx.x;
    const int tid = threadIdx.x;
    const int wid = tid >> 5;
    const int lane = tid & 31;
    const float* Qg = g_Q + ((size_t)bh * Tt + c * CH) * HDim;
    const float* Kg = g_K + ((size_t)bh * Tt + c * CH) * HDim;
    const float* Vg = g_V + ((size_t)bh * Tt + c * CH) * HDim;
    const float* Sg = g_sp + ((size_t)bh * NCH + c) * 4096;

    __half* sQh  = (__half*)(smem + OFF_QH2);
    __half* sQl  = (__half*)(smem + OFF_QL2);
    __half* sKh  = (__half*)(smem + OFF_KH2);
    __half* sKl  = (__half*)(smem + OFF_KL2);
    __half* sVh  = (__half*)(smem + OFF_VH2);
    __half* sVl  = (__half*)(smem + OFF_VL2);
    __half* sSph = (__half*)(smem + OFF_SPH2);
    __half* sSpl = (__half*)(smem + OFF_SPL2);
    __half* sAh  = (__half*)(smem + OFF_AH2);
    __half* sAl  = (__half*)(smem + OFF_AL2);

    // ---- load + convert (all row-major hi/lo, vectorized stores)
    for (int i = tid; i < 1024; i += 256) {
        int r = i >> 4;
        int c4 = (i & 15) << 2;
        float4 q = *(const float4*)(Qg + r * 64 + c4);
        float4 k = *(const float4*)(Kg + r * 64 + c4);
        float4 v = *(const float4*)(Vg + r * 64 + c4);
        float4 s = *(const float4*)(Sg + r * 64 + c4);
        {
            uint32_t h01 = packh(q.x, q.y), h23 = packh(q.z, q.w);
            float2 f01 = unpackh(h01), f23 = unpackh(h23);
            *(uint2*)(sQh + r * TPAD + c4) = make_uint2(h01, h23);
            *(uint2*)(sQl + r * TPAD + c4) =
                make_uint2(packh(q.x - f01.x, q.y - f01.y), packh(q.z - f23.x, q.w - f23.y));
        }
        {
            uint32_t h01 = packh(k.x, k.y), h23 = packh(k.z, k.w);
            float2 f01 = unpackh(h01), f23 = unpackh(h23);
            *(uint2*)(sKh + r * TPAD + c4) = make_uint2(h01, h23);
            *(uint2*)(sKl + r * TPAD + c4) =
                make_uint2(packh(k.x - f01.x, k.y - f01.y), packh(k.z - f23.x, k.w - f23.y));
        }
        {
            uint32_t h01 = packh(v.x, v.y), h23 = packh(v.z, v.w);
            float2 f01 = unpackh(h01), f23 = unpackh(h23);
            *(uint2*)(sVh + r * TPAD + c4) = make_uint2(h01, h23);
            *(uint2*)(sVl + r * TPAD + c4) =
                make_uint2(packh(v.x - f01.x, v.y - f01.y), packh(v.z - f23.x, v.w - f23.y));
        }
        {
            uint32_t h01 = packh(s.x, s.y), h23 = packh(s.z, s.w);
            float2 f01 = unpackh(h01), f23 = unpackh(h23);
            *(uint2*)(sSph + r * TPAD + c4) = make_uint2(h01, h23);
            *(uint2*)(sSpl + r * TPAD + c4) =
                make_uint2(packh(s.x - f01.x, s.y - f01.y), packh(s.z - f23.x, s.w - f23.y));
        }
    }
    __syncthreads();

    const int mw = (wid >> 1) * 16;
    const int nw = (wid & 1) * 32;
    const int lrow  = lane >> 2;
    const int lcol2 = (lane & 3) * 2;

    const uint32_t a_lane = (uint32_t)(((mw + ((lane >> 3) & 1) * 8 + (lane & 7)) * TPAD
                                        + (lane >> 4) * 8) * 2);
    const uint32_t b_lane = (uint32_t)(((nw + (lane >> 4) * 8 + (lane & 7)) * TPAD
                                        + ((lane >> 3) & 1) * 8) * 2);
    // trans B (V): rows s = ((lane>>3)&1)*8 + (lane&7); col p = nw + (lane>>4)*8
    const uint32_t bt_lane = (uint32_t)(((((lane >> 3) & 1) * 8 + (lane & 7)) * TPAD
                                         + nw + (lane >> 4) * 8) * 2);

    // ---- phase 1: scores (3-term)
    float a[4][4];
#pragma unroll
    for (int ni = 0; ni < 4; ni++)
#pragma unroll
        for (int r = 0; r < 4; r++) a[ni][r] = 0.0f;
#pragma unroll
    for (int kk = 0; kk < 64; kk += 16) {
        uint32_t qh[4], ql[4];
        uint32_t ad = sbase + OFF_QH2 + a_lane + (uint32_t)(kk * 2);
        ldmx4(qh, ad);
        ldmx4(ql, ad + (OFF_QL2 - OFF_QH2));
        uint32_t bkh[4][2], bkl[4][2];
#pragma unroll
        for (int np = 0; np < 2; np++) {
            uint32_t bd = sbase + OFF_KH2 + b_lane + (uint32_t)((np * 16 * TPAD + kk) * 2);
            uint32_t r4[4];
            ldmx4(r4, bd);
            bkh[np * 2][0] = r4[0]; bkh[np * 2][1] = r4[1];
            bkh[np * 2 + 1][0] = r4[2]; bkh[np * 2 + 1][1] = r4[3];
            ldmx4(r4, bd + (OFF_KL2 - OFF_KH2));
            bkl[np * 2][0] = r4[0]; bkl[np * 2][1] = r4[1];
            bkl[np * 2 + 1][0] = r4[2]; bkl[np * 2 + 1][1] = r4[3];
        }
#pragma unroll
        for (int ni = 0; ni < 4; ni++) {
            mma_f16(a[ni], qh, bkh[ni]);
            mma_f16(a[ni], qh, bkl[ni]);
            mma_f16(a[ni], ql, bkh[ni]);
        }
    }
    __syncthreads();   // K reads done before Am aliases overwrite

#pragma unroll
    for (int ni = 0; ni < 4; ni++)
#pragma unroll
        for (int r = 0; r < 4; r++) {
            int t = mw + lrow + (r >> 1) * 8;
            int s = nw + ni * 8 + lcol2 + (r & 1);
            float v = (s <= t) ? a[ni][r] : 0.0f;
            __half h = __float2half(v);
            sAh[t * TPAD + s] = h;
            sAl[t * TPAD + s] = __float2half(v - __half2float(h));
        }

    // ---- phase 2b: y += Q·Sp^T (3-term)
    float y[4][4];
#pragma unroll
    for (int ni = 0; ni < 4; ni++)
#pragma unroll
        for (int r = 0; r < 4; r++) y[ni][r] = 0.0f;
#pragma unroll
    for (int kk = 0; kk < 64; kk += 16) {
        uint32_t qh[4], ql[4];
        uint32_t ad = sbase + OFF_QH2 + a_lane + (uint32_t)(kk * 2);
        ldmx4(qh, ad);
        ldmx4(ql, ad + (OFF_QL2 - OFF_QH2));
        uint32_t bsh[4][2], bsl[4][2];
#pragma unroll
        for (int np = 0; np < 2; np++) {
            uint32_t bd = sbase + OFF_SPH2 + b_lane + (uint32_t)((np * 16 * TPAD + kk) * 2);
            uint32_t r4[4];
            ldmx4(r4, bd);
            bsh[np * 2][0] = r4[0]; bsh[np * 2][1] = r4[1];
            bsh[np * 2 + 1][0] = r4[2]; bsh[np * 2 + 1][1] = r4[3];
            ldmx4(r4, bd + (OFF_SPL2 - OFF_SPH2));
            bsl[np * 2][0] = r4[0]; bsl[np * 2][1] = r4[1];
            bsl[np * 2 + 1][0] = r4[2]; bsl[np * 2 + 1][1] = r4[3];
        }
#pragma unroll
        for (int ni = 0; ni < 4; ni++) {
            mma_f16(y[ni], qh, bsh[ni]);
            mma_f16(y[ni], qh, bsl[ni]);
            mma_f16(y[ni], ql, bsh[ni]);
        }
    }

    __syncthreads();   // Am published

    // ---- phase 2a: y += Am·V (3-term; V row-major, trans-loaded)
#pragma unroll
    for (int kk = 0; kk < 64; kk += 16) {
        uint32_t amh[4], aml[4];
        uint32_t ad = sbase + OFF_AH2 + a_lane + (uint32_t)(kk * 2);
        ldmx4(amh, ad);
        ldmx4(aml, ad + (OFF_AL2 - OFF_AH2));
        uint32_t bvh[4][2], bvl[4][2];
#pragma unroll
        for (int np = 0; np < 2; np++) {
            uint32_t bd = sbase + OFF_VH2 + bt_lane + (uint32_t)((kk * TPAD + np * 16) * 2);
            uint32_t r4[4];
            ldmx4t(r4, bd);
            bvh[np * 2][0] = r4[0]; bvh[np * 2][1] = r4[1];
            bvh[np * 2 + 1][0] = r4[2]; bvh[np * 2 + 1][1] = r4[3];
            ldmx4t(r4, bd + (OFF_VL2 - OFF_VH2));
            bvl[np * 2][0] = r4[0]; bvl[np * 2][1] = r4[1];
            bvl[np * 2 + 1][0] = r4[2]; bvl[np * 2 + 1][1] = r4[3];
        }
#pragma unroll
        for (int ni = 0; ni < 4; ni++) {
            mma_f16(y[ni], amh, bvh[ni]);
            mma_f16(y[ni], amh, bvl[ni]);
            mma_f16(y[ni], aml, bvh[ni]);
        }
    }

    // ---- epilogue: write Y as fp16 ROW-MAJOR into g_Y16 (m = b*T + t, k = h*64 + p)
    const int b = bh >> 4, h = bh & 15;
    const int mbase = b * Tt + c * CH;
#pragma unroll
    for (int ni = 0; ni < 4; ni++) {
        int p = nw + ni * 8 + lcol2;
        int k = h * HDim + p;
        int m0 = mbase + mw + lrow, m1 = m0 + 8;
        *(uint32_t*)(g_Y16 + (size_t)m0 * Dd + k) = packh(y[ni][0], y[ni][1]);
        *(uint32_t*)(g_Y16 + (size_t)m1 * Dd + k) = packh(y[ni][2], y[ni][3]);
    }
}

// ---------------------------------------------------------------------------
extern "C" void kernel_launch(void* const* d_in, const int* in_sizes, int n_in,
                              void* d_out, int out_size)
{
    const float* x  = (const float*)d_in[0];
    const float* Wq = (const float*)d_in[1];
    const float* bq = (const float*)d_in[2];
    const float* Wk = (const float*)d_in[3];
    const float* bk = (const float*)d_in[4];
    const float* Wv = (const float*)d_in[5];
    const float* bv = (const float*)d_in[6];
    const float* Wo = (const float*)d_in[7];
    const float* bo = (const float*)d_in[8];
    float* out = (float*)d_out;

    cudaFuncSetAttribute(tc_gemm, cudaFuncAttributeMaxDynamicSharedMemorySize, GEMM_SMEM);
    cudaFuncSetAttribute(chunk_sums_tc, cudaFuncAttributeMaxDynamicSharedMemorySize, CS_SMEM);
    cudaFuncSetAttribute(attn_tc, cudaFuncAttributeMaxDynamicSharedMemorySize, ATTN_SMEM);

    convert_x<<<BT * Dd / 4 / 256, 256>>>((const float4*)x);
    convert_w<<<dim3(Dd * Dd / 4 / 256, 4), 256>>>((const float4*)Wq, (const float4*)Wk,
                                                   (const float4*)Wv, (const float4*)Wo);
    tc_gemm<<<dim3(Dd / TN, BT / TM, 3), 256, GEMM_SMEM>>>(bq, bk, bv, nullptr, 0);
    chunk_sums_tc<<<dim3(NCH, BHn), 256, CS_SMEM>>>();
    prefix_kernel<<<dim3(BHn, 16), 256>>>();
    attn_tc<<<dim3(NCH, BHn), 256, ATTN_SMEM>>>();
    tc_gemm<<<dim3(Dd / TN, BT / TM, 1), 256, GEMM_SMEM>>>(bo, nullptr, nullptr, out, 1);
}

// round 17
// speedup vs baseline: 1.4955x; 1.4955x over previous
#include <cuda_runtime.h>
#include <cuda_fp16.h>
#include <cstdint>

// ---------------------------------------------------------------- problem dims
constexpr int Bb   = 2;
constexpr int Tt   = 2048;
constexpr int Dd   = 1024;
constexpr int Hh   = 16;
constexpr int HDim = 64;
constexpr int BT   = Bb * Tt;      // 4096
constexpr int BHn  = Bb * Hh;      // 32
constexpr int CH   = 64;           // chunk length (attention)
constexpr int NCH  = Tt / CH;      // 32

// ---------------------------------------------------------------- scratch
__device__ float  g_Q[BHn * Tt * HDim];
__device__ float  g_K[BHn * Tt * HDim];
__device__ float  g_V[BHn * Tt * HDim];
__device__ float  g_cs[BHn * NCH * HDim * HDim];
__device__ float  g_sp[BHn * NCH * HDim * HDim];
__device__ __half g_X16[BT * Dd];          // fp16 input activations
__device__ __half g_W16[4 * Dd * Dd];      // fp16 weights (q,k,v,o)
__device__ __half g_Y16[BT * Dd];          // fp16 attention output, row-major

extern __shared__ char dyn_smem[];

// ---------------------------------------------------------------- helpers
// pack two floats to fp16x2: low half = lo_val, high half = hi_val
__device__ __forceinline__ uint32_t packh(float lo_val, float hi_val) {
    uint32_t r;
    asm("cvt.rn.f16x2.f32 %0, %1, %2;" : "=r"(r) : "f"(hi_val), "f"(lo_val));
    return r;
}
__device__ __forceinline__ float2 unpackh(uint32_t h) {
    __half2 hh = *reinterpret_cast<__half2*>(&h);
    return __half22float2(hh);
}

__device__ __forceinline__ void mma_f16(float* c, const uint32_t* a, const uint32_t* b) {
    asm volatile(
        "mma.sync.aligned.m16n8k16.row.col.f32.f16.f16.f32 "
        "{%0,%1,%2,%3}, {%4,%5,%6,%7}, {%8,%9}, {%0,%1,%2,%3};"
        : "+f"(c[0]), "+f"(c[1]), "+f"(c[2]), "+f"(c[3])
        : "r"(a[0]), "r"(a[1]), "r"(a[2]), "r"(a[3]), "r"(b[0]), "r"(b[1]));
}

__device__ __forceinline__ void ldmx4(uint32_t* r, uint32_t saddr) {
    asm volatile("ldmatrix.sync.aligned.m8n8.x4.shared.b16 {%0,%1,%2,%3}, [%4];"
                 : "=r"(r[0]), "=r"(r[1]), "=r"(r[2]), "=r"(r[3]) : "r"(saddr));
}
__device__ __forceinline__ void ldmx4t(uint32_t* r, uint32_t saddr) {
    asm volatile("ldmatrix.sync.aligned.m8n8.x4.trans.shared.b16 {%0,%1,%2,%3}, [%4];"
                 : "=r"(r[0]), "=r"(r[1]), "=r"(r[2]), "=r"(r[3]) : "r"(saddr));
}

// ---------------------------------------------------------------- converters
__global__ __launch_bounds__(256) void convert_x(const float4* __restrict__ src)
{
    int i = blockIdx.x * 256 + threadIdx.x;          // over BT*Dd/4
    float4 v = src[i];
    ((uint2*)g_X16)[i] = make_uint2(packh(v.x, v.y), packh(v.z, v.w));
}
__global__ __launch_bounds__(256) void convert_w(const float4* __restrict__ w0,
                                                 const float4* __restrict__ w1,
                                                 const float4* __restrict__ w2,
                                                 const float4* __restrict__ w3)
{
    int z = blockIdx.y;
    const float4* src = (z == 0) ? w0 : (z == 1) ? w1 : (z == 2) ? w2 : w3;
    int i = blockIdx.x * 256 + threadIdx.x;          // over Dd*Dd/4
    float4 v = src[i];
    ((uint2*)g_W16)[(size_t)z * (Dd * Dd / 4) + i] = make_uint2(packh(v.x, v.y), packh(v.z, v.w));
}

// ---------------------------------------------------------------- tc_gemm cfg
constexpr int TM = 128, TN = 128, KC = 32;   // CTA tile + K chunk
constexpr int NKC = Dd / KC;                 // 32
constexpr int PAD_K = 40;                    // fp16 row stride (conflict-free)
constexpr int TILE_B = 128 * PAD_K * 2;      // 10240 bytes per fp16 tile
constexpr int OFF_A = 0;
constexpr int OFF_B = TILE_B;
constexpr int BUF_B = 2 * TILE_B;            // 20480 per stage
constexpr int STAGES = 3;
constexpr int GEMM_SMEM = STAGES * BUF_B;    // 61440 (dynamic, 3-stage cp.async)

// ---------------------------------------------------------------------------
// Tensor-core GEMM, fp16 operands, cp.async 3-stage pipeline:
//   out[m,n] = sum_k A16[m,k] * W16[widx][n,k] + bias[n]
// mode 0: A = g_X16, widx = z, dst = g_Q/g_K/g_V head-major fp32
// mode 1: A = g_Y16, widx = 3, dst = outp row-major fp32
// ---------------------------------------------------------------------------
__global__ __launch_bounds__(256) void tc_gemm(const float* __restrict__ b0p,
                                               const float* __restrict__ b1p,
                                               const float* __restrict__ b2p,
                                               float* __restrict__ outp,
                                               int mode)
{
    char* smem = dyn_smem;
    const int tid  = threadIdx.x;
    const int wid  = tid >> 5;
    const int lane = tid & 31;
    const int z    = blockIdx.z;
    const int bn = blockIdx.x * TN;
    const int bm = blockIdx.y * TM;
    const int widx = (mode == 0) ? z : 3;
    const float* bias = (z == 0) ? b0p : (z == 1) ? b1p : b2p;
    const __half* A16 = (mode == 0) ? g_X16 : g_Y16;
    const __half* W16 = g_W16 + (size_t)widx * Dd * Dd;

    uint32_t sbase;
    asm("{ .reg .u64 t; cvta.to.shared.u64 t, %1; cvt.u32.u64 %0, t; }"
        : "=r"(sbase) : "l"((const void*)smem));

    const int m0w = (wid >> 2) * 64;      // warp row offset
    const int n0w = (wid & 3) * 32;       // warp col offset
    const int lrow  = lane >> 2;
    const int lcol2 = (lane & 3) * 2;

    const uint32_t a_lane = (uint32_t)(((m0w + ((lane >> 3) & 1) * 8 + (lane & 7)) * PAD_K
                                        + (lane >> 4) * 8) * 2);
    const uint32_t b_lane = (uint32_t)(((n0w + (lane >> 4) * 8 + (lane & 7)) * PAD_K
                                        + ((lane >> 3) & 1) * 8) * 2);

    float c[4][4][4];
#pragma unroll
    for (int mi = 0; mi < 4; mi++)
#pragma unroll
        for (int ni = 0; ni < 4; ni++)
#pragma unroll
            for (int r = 0; r < 4; r++) c[mi][ni][r] = 0.0f;

    const int row_ld = tid >> 2;
    const int cg     = (tid & 3) * 8;

    auto issue_copy = [&](int ck) {
        const int k0 = ck * KC;
        const uint32_t bo = (uint32_t)((ck % STAGES) * BUF_B);
#pragma unroll
        for (int t = 0; t < 2; t++) {
            int row = row_ld + t * 64;
            uint32_t soff = (uint32_t)((row * PAD_K + cg) * 2);
            const __half* ga = A16 + (size_t)(bm + row) * Dd + k0 + cg;
            const __half* gb = W16 + (size_t)(bn + row) * Dd + k0 + cg;
            uint32_t sa = sbase + bo + OFF_A + soff;
            uint32_t sb = sbase + bo + OFF_B + soff;
            asm volatile("cp.async.cg.shared.global [%0], [%1], 16;" :: "r"(sa), "l"(ga));
            asm volatile("cp.async.cg.shared.global [%0], [%1], 16;" :: "r"(sb), "l"(gb));
        }
        asm volatile("cp.async.commit_group;" ::: "memory");
    };

    issue_copy(0);
    issue_copy(1);

    for (int ck = 0; ck < NKC; ck++) {
        if (ck + 2 < NKC) {
            asm volatile("cp.async.wait_group 1;" ::: "memory");
        } else {
            asm volatile("cp.async.wait_group 0;" ::: "memory");
        }
        __syncthreads();
        if (ck + 2 < NKC) issue_copy(ck + 2);

        const uint32_t bo = (uint32_t)((ck % STAGES) * BUF_B);
#pragma unroll
        for (int kk = 0; kk < KC; kk += 16) {
            uint32_t ah[4][4];
#pragma unroll
            for (int mi = 0; mi < 4; mi++)
                ldmx4(ah[mi], sbase + bo + OFF_A + a_lane + (uint32_t)((mi * 16 * PAD_K + kk) * 2));
            uint32_t bh[4][2];
#pragma unroll
            for (int np = 0; np < 2; np++) {
                uint32_t r[4];
                ldmx4(r, sbase + bo + OFF_B + b_lane + (uint32_t)((np * 16 * PAD_K + kk) * 2));
                bh[np * 2][0] = r[0]; bh[np * 2][1] = r[1];
                bh[np * 2 + 1][0] = r[2]; bh[np * 2 + 1][1] = r[3];
            }
#pragma unroll
            for (int mi = 0; mi < 4; mi++)
#pragma unroll
                for (int ni = 0; ni < 4; ni++)
                    mma_f16(c[mi][ni], ah[mi], bh[ni]);
        }
    }

    // ---- epilogue
#pragma unroll
    for (int mi = 0; mi < 4; mi++) {
        int row0 = bm + m0w + mi * 16 + lrow;
        int row1 = row0 + 8;
#pragma unroll
        for (int ni = 0; ni < 4; ni++) {
            int n = bn + n0w + ni * 8 + lcol2;
            float bb0 = bias[n], bb1 = bias[n + 1];
            float2 v0 = make_float2(c[mi][ni][0] + bb0, c[mi][ni][1] + bb1);
            float2 v1 = make_float2(c[mi][ni][2] + bb0, c[mi][ni][3] + bb1);
            if (mode == 0) {
                float* base = (z == 0) ? g_Q : (z == 1) ? g_K : g_V;
                int h = n >> 6, hd = n & 63;
                int batch0 = row0 >> 11, t0 = row0 & 2047;
                int batch1 = row1 >> 11, t1 = row1 & 2047;
                *(float2*)(base + (((size_t)(batch0 * Hh + h) * Tt) + t0) * HDim + hd) = v0;
                *(float2*)(base + (((size_t)(batch1 * Hh + h) * Tt) + t1) * HDim + hd) = v1;
            } else {
                *(float2*)(outp + (size_t)row0 * Dd + n) = v0;
                *(float2*)(outp + (size_t)row1 * Dd + n) = v1;
            }
        }
    }
}

// ---------------------------------------------------------------- tile cfg
constexpr int TPAD = 72;                     // 144B stride -> conflict-free ldmatrix
constexpr int T_TILE2 = 64 * TPAD * 2;       // 9216 B

// ---------------------------------------------------------------------------
// Tensor-core chunk sums: cs[p][n] = sum_t V[t][p] * K[t][n]
// K/V stored ROW-MAJOR hi/lo (vectorized stores); both fragments loaded with
// ldmatrix.trans. 3-term split -> fp32-grade. (Measured 20.7 us in R16.)
// ---------------------------------------------------------------------------
constexpr int OFF_CVH = 0;
constexpr int OFF_CVL = 1 * T_TILE2;
constexpr int OFF_CKH = 2 * T_TILE2;
constexpr int OFF_CKL = 3 * T_TILE2;
constexpr int CS_SMEM = 4 * T_TILE2;         // 36864 B

__global__ __launch_bounds__(256) void chunk_sums_tc()
{
    char* smem = dyn_smem;
    uint32_t sbase;
    asm("{ .reg .u64 t; cvta.to.shared.u64 t, %1; cvt.u32.u64 %0, t; }"
        : "=r"(sbase) : "l"((const void*)smem));
    const int bh = blockIdx.y, c = blockIdx.x;
    const int tid = threadIdx.x;
    const int wid = tid >> 5;
    const int lane = tid & 31;
    const float* Kg = g_K + ((size_t)bh * Tt + c * CH) * HDim;
    const float* Vg = g_V + ((size_t)bh * Tt + c * CH) * HDim;

    __half* sVh = (__half*)(smem + OFF_CVH);
    __half* sVl = (__half*)(smem + OFF_CVL);
    __half* sKh = (__half*)(smem + OFF_CKH);
    __half* sKl = (__half*)(smem + OFF_CKL);

    for (int i = tid; i < 1024; i += 256) {
        int r = i >> 4;               // t 0..63
        int c4 = (i & 15) << 2;       // col base (p / n)
        float4 v = *(const float4*)(Vg + r * 64 + c4);
        float4 k = *(const float4*)(Kg + r * 64 + c4);
        {
            uint32_t h01 = packh(v.x, v.y), h23 = packh(v.z, v.w);
            float2 f01 = unpackh(h01), f23 = unpackh(h23);
            *(uint2*)(sVh + r * TPAD + c4) = make_uint2(h01, h23);
            *(uint2*)(sVl + r * TPAD + c4) =
                make_uint2(packh(v.x - f01.x, v.y - f01.y), packh(v.z - f23.x, v.w - f23.y));
        }
        {
            uint32_t h01 = packh(k.x, k.y), h23 = packh(k.z, k.w);
            float2 f01 = unpackh(h01), f23 = unpackh(h23);
            *(uint2*)(sKh + r * TPAD + c4) = make_uint2(h01, h23);
            *(uint2*)(sKl + r * TPAD + c4) =
                make_uint2(packh(k.x - f01.x, k.y - f01.y), packh(k.z - f23.x, k.w - f23.y));
        }
    }
    __syncthreads();

    const int mw = (wid >> 1) * 16;       // p base
    const int nw = (wid & 1) * 32;        // n base
    const int lrow  = lane >> 2;
    const int lcol2 = (lane & 3) * 2;

    const uint32_t at_lane = (uint32_t)((((lane >> 4) * 8 + (lane & 7)) * TPAD
                                         + mw + ((lane >> 3) & 1) * 8) * 2);
    const uint32_t bt_lane = (uint32_t)(((((lane >> 3) & 1) * 8 + (lane & 7)) * TPAD
                                         + nw + (lane >> 4) * 8) * 2);

    float acc[4][4];
#pragma unroll
    for (int ni = 0; ni < 4; ni++)
#pragma unroll
        for (int r = 0; r < 4; r++) acc[ni][r] = 0.0f;
#pragma unroll
    for (int kk = 0; kk < 64; kk += 16) {
        uint32_t vh[4], vl[4];
        uint32_t ad = sbase + OFF_CVH + at_lane + (uint32_t)(kk * TPAD * 2);
        ldmx4t(vh, ad);
        ldmx4t(vl, ad + (OFF_CVL - OFF_CVH));
        uint32_t kh[4][2], kl[4][2];
#pragma unroll
        for (int np = 0; np < 2; np++) {
            uint32_t bd = sbase + OFF_CKH + bt_lane + (uint32_t)((kk * TPAD + np * 16) * 2);
            uint32_t r4[4];
            ldmx4t(r4, bd);
            kh[np * 2][0] = r4[0]; kh[np * 2][1] = r4[1];
            kh[np * 2 + 1][0] = r4[2]; kh[np * 2 + 1][1] = r4[3];
            ldmx4t(r4, bd + (OFF_CKL - OFF_CKH));
            kl[np * 2][0] = r4[0]; kl[np * 2][1] = r4[1];
            kl[np * 2 + 1][0] = r4[2]; kl[np * 2 + 1][1] = r4[3];
        }
#pragma unroll
        for (int ni = 0; ni < 4; ni++) {
            mma_f16(acc[ni], vh, kh[ni]);
            mma_f16(acc[ni], vh, kl[ni]);
            mma_f16(acc[ni], vl, kh[ni]);
        }
    }

    float* dst = g_cs + ((size_t)bh * NCH + c) * 4096;
#pragma unroll
    for (int ni = 0; ni < 4; ni++) {
        int n = nw + ni * 8 + lcol2;
        int p0 = mw + lrow, p1 = p0 + 8;
        *(float2*)(dst + p0 * 64 + n) = make_float2(acc[ni][0], acc[ni][1]);
        *(float2*)(dst + p1 * 64 + n) = make_float2(acc[ni][2], acc[ni][3]);
    }
}

// ---------------------------------------------------------------------------
// Exclusive prefix over chunks (parallelized: 512 blocks)
// ---------------------------------------------------------------------------
__global__ __launch_bounds__(256) void prefix_kernel()
{
    const int bh = blockIdx.x;
    const int e = blockIdx.y * 256 + threadIdx.x;
    float acc = 0.0f;
#pragma unroll
    for (int c = 0; c < NCH; c++) {
        size_t off = ((size_t)bh * NCH + c) * 4096 + e;
        g_sp[off] = acc;
        acc += g_cs[off];
    }
}

// ---------------------------------------------------------------------------
// Tensor-core intra-chunk attention (R12 config — measured 24.5 us):
//   scores A[t][s] = mask(Q[t]·K[s]);  Y[t][p] = A·V + Q·Sp^T
// 2-term split on left operands (Q, Am); K/V/Sp single fp16.
// V transposed via scalar stores (NOT trans-ldmatrix — R16 showed that path
// regresses attn ~5x). Output fp16 row-major to g_Y16.
// ---------------------------------------------------------------------------
constexpr int OFF_QH2 = 0;
constexpr int OFF_QL2 = 1 * T_TILE2;
constexpr int OFF_K2  = 2 * T_TILE2;
constexpr int OFF_VT2 = 3 * T_TILE2;
constexpr int OFF_SP2 = 4 * T_TILE2;
constexpr int OFF_AH2 = 5 * T_TILE2;
constexpr int OFF_AL2 = 6 * T_TILE2;
constexpr int ATTN_SMEM = 7 * T_TILE2;       // 64512 B

__global__ __launch_bounds__(256) void attn_tc()
{
    char* smem = dyn_smem;
    uint32_t sbase;
    asm("{ .reg .u64 t; cvta.to.shared.u64 t, %1; cvt.u32.u64 %0, t; }"
        : "=r"(sbase) : "l"((const void*)smem));
    const int bh = blockIdx.y, c = blockIdx.x;
    const int tid = threadIdx.x;
    const int wid = tid >> 5;
    const int lane = tid & 31;
    const float* Qg = g_Q + ((size_t)bh * Tt + c * CH) * HDim;
    const float* Kg = g_K + ((size_t)bh * Tt + c * CH) * HDim;
    const float* Vg = g_V + ((size_t)bh * Tt + c * CH) * HDim;
    const float* Sg = g_sp + ((size_t)bh * NCH + c) * 4096;

    __half* sQh = (__half*)(smem + OFF_QH2);
    __half* sQl = (__half*)(smem + OFF_QL2);
    __half* sK  = (__half*)(smem + OFF_K2);
    __half* sVt = (__half*)(smem + OFF_VT2);
    __half* sSp = (__half*)(smem + OFF_SP2);
    __half* sAh = (__half*)(smem + OFF_AH2);
    __half* sAl = (__half*)(smem + OFF_AL2);

    // ---- load + convert
    for (int i = tid; i < 1024; i += 256) {
        int r = i >> 4;               // row 0..63
        int c4 = (i & 15) << 2;       // col base
        float4 q = *(const float4*)(Qg + r * 64 + c4);
        float4 k = *(const float4*)(Kg + r * 64 + c4);
        float4 v = *(const float4*)(Vg + r * 64 + c4);
        float4 s = *(const float4*)(Sg + r * 64 + c4);
        // Q hi/lo
        uint32_t h01 = packh(q.x, q.y), h23 = packh(q.z, q.w);
        float2 f01 = unpackh(h01), f23 = unpackh(h23);
        *(uint2*)(sQh + r * TPAD + c4) = make_uint2(h01, h23);
        *(uint2*)(sQl + r * TPAD + c4) =
            make_uint2(packh(q.x - f01.x, q.y - f01.y), packh(q.z - f23.x, q.w - f23.y));
        // K single fp16
        *(uint2*)(sK + r * TPAD + c4) = make_uint2(packh(k.x, k.y), packh(k.z, k.w));
        // V transposed: sVt[p][s], p = c4+j, s = r (scalar stores)
        sVt[(c4 + 0) * TPAD + r] = __float2half(v.x);
        sVt[(c4 + 1) * TPAD + r] = __float2half(v.y);
        sVt[(c4 + 2) * TPAD + r] = __float2half(v.z);
        sVt[(c4 + 3) * TPAD + r] = __float2half(v.w);
        // Sp[p][n] single fp16
        *(uint2*)(sSp + r * TPAD + c4) = make_uint2(packh(s.x, s.y), packh(s.z, s.w));
    }
    __syncthreads();

    const int mw = (wid >> 1) * 16;       // warp M (t) base
    const int nw = (wid & 1) * 32;        // warp N (s / p) base
    const int lrow  = lane >> 2;
    const int lcol2 = (lane & 3) * 2;

    const uint32_t a_lane = (uint32_t)(((mw + ((lane >> 3) & 1) * 8 + (lane & 7)) * TPAD
                                        + (lane >> 4) * 8) * 2);
    const uint32_t b_lane = (uint32_t)(((nw + (lane >> 4) * 8 + (lane & 7)) * TPAD
                                        + ((lane >> 3) & 1) * 8) * 2);

    // ---- phase 1: scores (2-term on Q)
    float a[4][4];
#pragma unroll
    for (int ni = 0; ni < 4; ni++)
#pragma unroll
        for (int r = 0; r < 4; r++) a[ni][r] = 0.0f;
#pragma unroll
    for (int kk = 0; kk < 64; kk += 16) {
        uint32_t qh[4], ql[4];
        uint32_t ad = sbase + OFF_QH2 + a_lane + (uint32_t)(kk * 2);
        ldmx4(qh, ad);
        ldmx4(ql, ad + (OFF_QL2 - OFF_QH2));
        uint32_t bk[4][2];
#pragma unroll
        for (int np = 0; np < 2; np++) {
            uint32_t r4[4];
            ldmx4(r4, sbase + OFF_K2 + b_lane + (uint32_t)((np * 16 * TPAD + kk) * 2));
            bk[np * 2][0] = r4[0]; bk[np * 2][1] = r4[1];
            bk[np * 2 + 1][0] = r4[2]; bk[np * 2 + 1][1] = r4[3];
        }
#pragma unroll
        for (int ni = 0; ni < 4; ni++) {
            mma_f16(a[ni], qh, bk[ni]);
            mma_f16(a[ni], ql, bk[ni]);
        }
    }

    // ---- write masked scores (hi/lo split) to sAh/sAl
#pragma unroll
    for (int ni = 0; ni < 4; ni++)
#pragma unroll
        for (int r = 0; r < 4; r++) {
            int t = mw + lrow + (r >> 1) * 8;
            int s = nw + ni * 8 + lcol2 + (r & 1);
            float v = (s <= t) ? a[ni][r] : 0.0f;
            __half h = __float2half(v);
            sAh[t * TPAD + s] = h;
            sAl[t * TPAD + s] = __float2half(v - __half2float(h));
        }

    // ---- phase 2b first (independent of Am): y += Q·Sp^T
    float y[4][4];
#pragma unroll
    for (int ni = 0; ni < 4; ni++)
#pragma unroll
        for (int r = 0; r < 4; r++) y[ni][r] = 0.0f;
#pragma unroll
    for (int kk = 0; kk < 64; kk += 16) {
        uint32_t qh[4], ql[4];
        uint32_t ad = sbase + OFF_QH2 + a_lane + (uint32_t)(kk * 2);
        ldmx4(qh, ad);
        ldmx4(ql, ad + (OFF_QL2 - OFF_QH2));
        uint32_t bs[4][2];
#pragma unroll
        for (int np = 0; np < 2; np++) {
            uint32_t r4[4];
            ldmx4(r4, sbase + OFF_SP2 + b_lane + (uint32_t)((np * 16 * TPAD + kk) * 2));
            bs[np * 2][0] = r4[0]; bs[np * 2][1] = r4[1];
            bs[np * 2 + 1][0] = r4[2]; bs[np * 2 + 1][1] = r4[3];
        }
#pragma unroll
        for (int ni = 0; ni < 4; ni++) {
            mma_f16(y[ni], qh, bs[ni]);
            mma_f16(y[ni], ql, bs[ni]);
        }
    }

    __syncthreads();   // Am published by all warps

    // ---- phase 2a: y += Am·V  (2-term on Am; B = Vt[p][s])
#pragma unroll
    for (int kk = 0; kk < 64; kk += 16) {
        uint32_t amh[4], aml[4];
        uint32_t ad = sbase + OFF_AH2 + a_lane + (uint32_t)(kk * 2);
        ldmx4(amh, ad);
        ldmx4(aml, ad + (OFF_AL2 - OFF_AH2));
        uint32_t bv[4][2];
#pragma unroll
        for (int np = 0; np < 2; np++) {
            uint32_t r4[4];
            ldmx4(r4, sbase + OFF_VT2 + b_lane + (uint32_t)((np * 16 * TPAD + kk) * 2));
            bv[np * 2][0] = r4[0]; bv[np * 2][1] = r4[1];
            bv[np * 2 + 1][0] = r4[2]; bv[np * 2 + 1][1] = r4[3];
        }
#pragma unroll
        for (int ni = 0; ni < 4; ni++) {
            mma_f16(y[ni], amh, bv[ni]);
            mma_f16(y[ni], aml, bv[ni]);
        }
    }

    // ---- epilogue: write Y fp16 ROW-MAJOR (m = b*T + t, k = h*64 + p)
    const int b = bh >> 4, h = bh & 15;
    const int mbase = b * Tt + c * CH;
#pragma unroll
    for (int ni = 0; ni < 4; ni++) {
        int p = nw + ni * 8 + lcol2;
        int k = h * HDim + p;
        int m0 = mbase + mw + lrow, m1 = m0 + 8;
        *(uint32_t*)(g_Y16 + (size_t)m0 * Dd + k) = packh(y[ni][0], y[ni][1]);
        *(uint32_t*)(g_Y16 + (size_t)m1 * Dd + k) = packh(y[ni][2], y[ni][3]);
    }
}

// ---------------------------------------------------------------------------
extern "C" void kernel_launch(void* const* d_in, const int* in_sizes, int n_in,
                              void* d_out, int out_size)
{
    const float* x  = (const float*)d_in[0];
    const float* Wq = (const float*)d_in[1];
    const float* bq = (const float*)d_in[2];
    const float* Wk = (const float*)d_in[3];
    const float* bk = (const float*)d_in[4];
    const float* Wv = (const float*)d_in[5];
    const float* bv = (const float*)d_in[6];
    const float* Wo = (const float*)d_in[7];
    const float* bo = (const float*)d_in[8];
    float* out = (float*)d_out;

    cudaFuncSetAttribute(tc_gemm, cudaFuncAttributeMaxDynamicSharedMemorySize, GEMM_SMEM);
    cudaFuncSetAttribute(chunk_sums_tc, cudaFuncAttributeMaxDynamicSharedMemorySize, CS_SMEM);
    cudaFuncSetAttribute(attn_tc, cudaFuncAttributeMaxDynamicSharedMemorySize, ATTN_SMEM);

    convert_x<<<BT * Dd / 4 / 256, 256>>>((const float4*)x);
    convert_w<<<dim3(Dd * Dd / 4 / 256, 4), 256>>>((const float4*)Wq, (const float4*)Wk,
                                                   (const float4*)Wv, (const float4*)Wo);
    tc_gemm<<<dim3(Dd / TN, BT / TM, 3), 256, GEMM_SMEM>>>(bq, bk, bv, nullptr, 0);
    chunk_sums_tc<<<dim3(NCH, BHn), 256, CS_SMEM>>>();
    prefix_kernel<<<dim3(BHn, 16), 256>>>();
    attn_tc<<<dim3(NCH, BHn), 256, ATTN_SMEM>>>();
    tc_gemm<<<dim3(Dd / TN, BT / TM, 1), 256, GEMM_SMEM>>>(bo, nullptr, nullptr, out, 1);
}